// round 5
// baseline (speedup 1.0000x reference)
#include <cuda_runtime.h>
#include <math.h>

// ---------------------------------------------------------------------------
// FastVecKM: out = normalize_rows( complex-demodulated (eB (eB^T eA)) )
//   N=65536 pts, ENC_DIM=512 (2D=1024), P=4096 (2P=8192)
// Two fp32 GEMMs (~2.2 TFLOP) + trig encode + elementwise finalize.
// Scratch kept to 2.29 GB total so aarch64 host-shadow .bss relocations fit.
// ---------------------------------------------------------------------------

#define NPTS   65536
#define DENC   512
#define PDIM   4096
#define TWO_D  1024
#define TWO_P  8192

#define BM 128
#define BN 128
#define BK 16

typedef unsigned long long u64;

// Scratch (allocation-free __device__ globals)
__device__ float g_eA[(u64)NPTS * TWO_D];    // 256 MB : N x 1024, n-major (cos|sin of pA)
__device__ float g_eB[(u64)NPTS * TWO_P];    // 2 GB   : N x 8192, n-major (cos|sin of pB)
__device__ float g_C1[(u64)TWO_P * TWO_D];   // 32 MB  : M = eB^T eA  (8192 x 1024)

// ---- packed fp32 helpers (sm_103a FFMA2) ----------------------------------
__device__ __forceinline__ u64 ffma2(u64 a, u64 b, u64 c) {
    u64 d;
    asm("fma.rn.f32x2 %0, %1, %2, %3;" : "=l"(d) : "l"(a), "l"(b), "l"(c));
    return d;
}
__device__ __forceinline__ u64 dup2(float x) {
    u64 r;
    asm("mov.b64 %0, {%1, %2};" : "=l"(r) : "f"(x), "f"(x));
    return r;
}
__device__ __forceinline__ float2 unpack2(u64 v) {
    float2 r;
    asm("mov.b64 {%0, %1}, %2;" : "=f"(r.x), "=f"(r.y) : "l"(v));
    return r;
}

// ---------------------------------------------------------------------------
// Encode: E[n][j] = cos(ph), E[n][D+j] = sin(ph), ph = (pts[n]/0.05) . W[:,j]
// n-major (row-major N x 2D). j fastest -> coalesced stores.
// ---------------------------------------------------------------------------
__global__ void encode_cols(const float* __restrict__ pts, const float* __restrict__ W,
                            float* __restrict__ E, int D, int logD)
{
    long long idx = (long long)blockIdx.x * blockDim.x + threadIdx.x;
    int n = (int)(idx >> logD);
    int j = (int)(idx & (D - 1));
    float x0 = pts[3 * n + 0] * 20.0f;   // 1/RADIUS
    float x1 = pts[3 * n + 1] * 20.0f;
    float x2 = pts[3 * n + 2] * 20.0f;
    float ph = x0 * W[j] + x1 * W[D + j] + x2 * W[2 * D + j];
    float s, c;
    sincosf(ph, &s, &c);
    u64 base = (u64)n * (u64)(2 * D);
    E[base + j]     = c;
    E[base + D + j] = s;
}

// ---------------------------------------------------------------------------
// Shared FFMA2 microkernel body (reads As/Bs K-major slabs).
// acc: 8 m-rows x 4 packed-f32x2 n-cols per thread.
// ---------------------------------------------------------------------------
#define MICRO_KSTEP(ASB, BSB, k)                                              \
    {                                                                         \
        float4 a0 = *(const float4*)&ASB[k][am];                              \
        float4 a1 = *(const float4*)&ASB[k][am + 4];                          \
        ulonglong2 t0 = *(const ulonglong2*)&BSB[k][bn];                      \
        ulonglong2 t1 = *(const ulonglong2*)&BSB[k][bn + 4];                  \
        u64 bb0 = t0.x, bb1 = t0.y, bb2 = t1.x, bb3 = t1.y;                   \
        u64 ad;                                                               \
        GEMM_ROW(0, a0.x) GEMM_ROW(1, a0.y) GEMM_ROW(2, a0.z) GEMM_ROW(3, a0.w) \
        GEMM_ROW(4, a1.x) GEMM_ROW(5, a1.y) GEMM_ROW(6, a1.z) GEMM_ROW(7, a1.w) \
    }

#define GEMM_ROW(i, av) ad = dup2(av);            \
    acc[i][0] = ffma2(ad, bb0, acc[i][0]);        \
    acc[i][1] = ffma2(ad, bb1, acc[i][1]);        \
    acc[i][2] = ffma2(ad, bb2, acc[i][2]);        \
    acc[i][3] = ffma2(ad, bb3, acc[i][3]);

// ---------------------------------------------------------------------------
// TN SGEMM:  C[m][n] = sum_k A[k*lda + m] * B[k*ldb + n]
// Both operands K-major. 128x128x16, 256 thr, 8x8 microtile, double buffer.
// ---------------------------------------------------------------------------
__global__ __launch_bounds__(256, 2)
void gemm_tn(const float* __restrict__ A, const float* __restrict__ B,
             float* __restrict__ C, int K, int lda, int ldb, int ldc)
{
    __shared__ __align__(16) float As[2][BK][BM];
    __shared__ __align__(16) float Bs[2][BK][BN];

    const int tid = threadIdx.x;
    const int m0 = blockIdx.y * BM;
    const int n0 = blockIdx.x * BN;

    const int lr = tid >> 5;             // 0..7  (k row)
    const int lc = (tid & 31) << 2;      // 0..124 (float4 col)

    const float* aPtr = A + (size_t)lr * lda + (size_t)(m0 + lc);
    const float* bPtr = B + (size_t)lr * ldb + (size_t)(n0 + lc);
    const size_t aStep = (size_t)BK * lda, bStep = (size_t)BK * ldb;
    const size_t a8 = (size_t)8 * lda,    b8 = (size_t)8 * ldb;

    const int am = (tid >> 4) << 3;
    const int bn = (tid & 15) << 3;

    u64 acc[8][4];
#pragma unroll
    for (int i = 0; i < 8; i++)
#pragma unroll
        for (int j = 0; j < 4; j++) acc[i][j] = 0ull;

    float4 ra0 = *(const float4*)(aPtr);
    float4 ra1 = *(const float4*)(aPtr + a8);
    float4 rb0 = *(const float4*)(bPtr);
    float4 rb1 = *(const float4*)(bPtr + b8);
    *(float4*)&As[0][lr][lc]     = ra0;
    *(float4*)&As[0][lr + 8][lc] = ra1;
    *(float4*)&Bs[0][lr][lc]     = rb0;
    *(float4*)&Bs[0][lr + 8][lc] = rb1;
    __syncthreads();

    const int nk = K / BK;
    int buf = 0;
    for (int kt = 0; kt < nk; kt++) {
        if (kt + 1 < nk) {
            const float* ap = aPtr + (size_t)(kt + 1) * aStep;
            const float* bp = bPtr + (size_t)(kt + 1) * bStep;
            ra0 = *(const float4*)(ap);
            ra1 = *(const float4*)(ap + a8);
            rb0 = *(const float4*)(bp);
            rb1 = *(const float4*)(bp + b8);
        }
#pragma unroll
        for (int k = 0; k < BK; k++) MICRO_KSTEP(As[buf], Bs[buf], k)
        if (kt + 1 < nk) {
            int nb = buf ^ 1;
            *(float4*)&As[nb][lr][lc]     = ra0;
            *(float4*)&As[nb][lr + 8][lc] = ra1;
            *(float4*)&Bs[nb][lr][lc]     = rb0;
            *(float4*)&Bs[nb][lr + 8][lc] = rb1;
        }
        __syncthreads();
        buf ^= 1;
    }

    float* cPtr = C + (size_t)(m0 + am) * ldc + (size_t)(n0 + bn);
#pragma unroll
    for (int i = 0; i < 8; i++) {
        float2 p0 = unpack2(acc[i][0]);
        float2 p1 = unpack2(acc[i][1]);
        float2 p2 = unpack2(acc[i][2]);
        float2 p3 = unpack2(acc[i][3]);
        *(float4*)(cPtr)     = make_float4(p0.x, p0.y, p1.x, p1.y);
        *(float4*)(cPtr + 4) = make_float4(p2.x, p2.y, p3.x, p3.y);
        cPtr += ldc;
    }
}

// ---------------------------------------------------------------------------
// NN SGEMM:  C[m][n] = sum_k A[m*lda + k] * B[k*ldb + n]
// A is row(m)-major; transposing loader stages it into K-major smem.
// ---------------------------------------------------------------------------
__global__ __launch_bounds__(256, 2)
void gemm_nn(const float* __restrict__ A, const float* __restrict__ B,
             float* __restrict__ C, int K, int lda, int ldb, int ldc)
{
    __shared__ __align__(16) float As[2][BK][BM];
    __shared__ __align__(16) float Bs[2][BK][BN];

    const int tid = threadIdx.x;
    const int m0 = blockIdx.y * BM;
    const int n0 = blockIdx.x * BN;

    // A loader: rows ar, ar+64 of the 128-row M-slab; 4 k-cols each
    const int ar = tid >> 2;             // 0..63
    const int ac = (tid & 3) << 2;       // 0,4,8,12
    const float* aPtr = A + (size_t)(m0 + ar) * lda + (size_t)ac;
    const size_t a64 = (size_t)64 * lda;

    // B loader: same as TN
    const int lr = tid >> 5;
    const int lc = (tid & 31) << 2;
    const float* bPtr = B + (size_t)lr * ldb + (size_t)(n0 + lc);
    const size_t bStep = (size_t)BK * ldb;
    const size_t b8 = (size_t)8 * ldb;

    const int am = (tid >> 4) << 3;
    const int bn = (tid & 15) << 3;

    u64 acc[8][4];
#pragma unroll
    for (int i = 0; i < 8; i++)
#pragma unroll
        for (int j = 0; j < 4; j++) acc[i][j] = 0ull;

    float4 ra0 = *(const float4*)(aPtr);
    float4 ra1 = *(const float4*)(aPtr + a64);
    float4 rb0 = *(const float4*)(bPtr);
    float4 rb1 = *(const float4*)(bPtr + b8);
    As[0][ac + 0][ar] = ra0.x; As[0][ac + 1][ar] = ra0.y;
    As[0][ac + 2][ar] = ra0.z; As[0][ac + 3][ar] = ra0.w;
    As[0][ac + 0][ar + 64] = ra1.x; As[0][ac + 1][ar + 64] = ra1.y;
    As[0][ac + 2][ar + 64] = ra1.z; As[0][ac + 3][ar + 64] = ra1.w;
    *(float4*)&Bs[0][lr][lc]     = rb0;
    *(float4*)&Bs[0][lr + 8][lc] = rb1;
    __syncthreads();

    const int nk = K / BK;
    int buf = 0;
    for (int kt = 0; kt < nk; kt++) {
        if (kt + 1 < nk) {
            const float* ap = aPtr + (size_t)(kt + 1) * BK;
            const float* bp = bPtr + (size_t)(kt + 1) * bStep;
            ra0 = *(const float4*)(ap);
            ra1 = *(const float4*)(ap + a64);
            rb0 = *(const float4*)(bp);
            rb1 = *(const float4*)(bp + b8);
        }
#pragma unroll
        for (int k = 0; k < BK; k++) MICRO_KSTEP(As[buf], Bs[buf], k)
        if (kt + 1 < nk) {
            int nb = buf ^ 1;
            As[nb][ac + 0][ar] = ra0.x; As[nb][ac + 1][ar] = ra0.y;
            As[nb][ac + 2][ar] = ra0.z; As[nb][ac + 3][ar] = ra0.w;
            As[nb][ac + 0][ar + 64] = ra1.x; As[nb][ac + 1][ar + 64] = ra1.y;
            As[nb][ac + 2][ar + 64] = ra1.z; As[nb][ac + 3][ar + 64] = ra1.w;
            *(float4*)&Bs[nb][lr][lc]     = rb0;
            *(float4*)&Bs[nb][lr + 8][lc] = rb1;
        }
        __syncthreads();
        buf ^= 1;
    }

    float* cPtr = C + (size_t)(m0 + am) * ldc + (size_t)(n0 + bn);
#pragma unroll
    for (int i = 0; i < 8; i++) {
        float2 p0 = unpack2(acc[i][0]);
        float2 p1 = unpack2(acc[i][1]);
        float2 p2 = unpack2(acc[i][2]);
        float2 p3 = unpack2(acc[i][3]);
        *(float4*)(cPtr)     = make_float4(p0.x, p0.y, p1.x, p1.y);
        *(float4*)(cPtr + 4) = make_float4(p2.x, p2.y, p3.x, p3.y);
        cPtr += ldc;
    }
}

// ---------------------------------------------------------------------------
// Finalize (in place on G = d_out): re/im, per-row L2 norm, scale.
// ---------------------------------------------------------------------------
__global__ void finalize_kernel(float* __restrict__ G, const float* __restrict__ eA)
{
    __shared__ float red[256];
    int n = blockIdx.x;
    int t = threadIdx.x;
    u64 base = (u64)n * TWO_D;

    float re[2], im[2];
    float acc = 0.f;
#pragma unroll
    for (int q = 0; q < 2; q++) {
        int j = t + q * 256;
        float Gc = G[base + j];
        float Gs = G[base + DENC + j];
        float cA = eA[base + j];
        float sA = eA[base + DENC + j];
        float den = cA * cA + sA * sA;
        float r  = (Gc * cA + Gs * sA) / den;
        float ii = (Gs * cA - Gc * sA) / den;
        re[q] = r; im[q] = ii;
        acc += r * r + ii * ii;
    }
    red[t] = acc;
    __syncthreads();
#pragma unroll
    for (int s = 128; s > 0; s >>= 1) {
        if (t < s) red[t] += red[t + s];
        __syncthreads();
    }
    float scale = 22.62741699796952f / sqrtf(red[0]);   // sqrt(512)/nrm
#pragma unroll
    for (int q = 0; q < 2; q++) {
        int j = t + q * 256;
        G[base + j]        = re[q] * scale;
        G[base + DENC + j] = im[q] * scale;
    }
}

// ---------------------------------------------------------------------------
extern "C" void kernel_launch(void* const* d_in, const int* in_sizes, int n_in,
                              void* d_out, int out_size)
{
    const float* pts = (const float*)d_in[0];   // 65536 x 3
    const float* A   = (const float*)d_in[1];   // 3 x 512
    const float* B   = (const float*)d_in[2];   // 3 x 4096
    float* out = (float*)d_out;                 // 65536 x 1024 fp32

    float *eA, *eB, *C1;
    cudaGetSymbolAddress((void**)&eA, g_eA);
    cudaGetSymbolAddress((void**)&eB, g_eB);
    cudaGetSymbolAddress((void**)&C1, g_C1);

    const int T = 256;

    // encode: eA (N x 1024), eB (N x 8192), both n-major
    encode_cols<<<((long long)NPTS * DENC) / T, T>>>(pts, A, eA, DENC, 9);
    encode_cols<<<((long long)NPTS * PDIM) / T, T>>>(pts, B, eB, PDIM, 12);

    dim3 blk(256);

    // GEMM1 (TN): C1[p][d] = sum_n eB[n][p] * eA[n][d]     (K = 65536)
    dim3 g1(TWO_D / BN, TWO_P / BM);    // (8, 64)
    gemm_tn<<<g1, blk>>>(eB, eA, C1, NPTS, TWO_P, TWO_D, TWO_D);

    // GEMM2 (NN): G[n][d] = sum_p eB[n][p] * C1[p][d]      (K = 8192)
    dim3 g2(TWO_D / BN, NPTS / BM);     // (8, 512)
    gemm_nn<<<g2, blk>>>(eB, C1, out, TWO_P, TWO_P, TWO_D, TWO_D);

    // re/im + row-norm + scale, in place on d_out
    finalize_kernel<<<NPTS, 256>>>(out, eA);
}